// round 4
// baseline (speedup 1.0000x reference)
#include <cuda_runtime.h>
#include <math.h>

// Problem constants (fixed by the reference)
#define NN 50000
#define NE 800000
#define INC 128
#define OUTC 64
#define HEADS 4
#define HC (HEADS * OUTC)   // 256
#define NEG_SLOPE 0.2f

// ---------------- scratch (device globals) -----------------------------------
__device__ float g_h[(size_t)NN * HC];      // projected features [N,256]
__device__ float g_asrc[NN * HEADS];        // per-node att halves
__device__ float g_adst[NN * HEADS];
__device__ int   g_deg[NN];                 // in-degree (real edges only)
__device__ int   g_off[NN + 1];             // CSR offsets
__device__ int   g_pos[NN];                 // fill cursors
__device__ int   g_csr_src[NE];             // src per CSR slot
__device__ int   g_is64;                    // edge_index dtype flag

// ---------------- helpers -----------------------------------------------------
__device__ __forceinline__ float lrelu(float v) {
    return v >= 0.0f ? v : NEG_SLOPE * v;
}

__device__ __forceinline__ int edge_at(const void* ei, long long idx) {
    if (g_is64) return (int)((const long long*)ei)[idx];
    return ((const int*)ei)[idx];
}

__device__ __forceinline__ unsigned long long pack2(float lo, float hi) {
    unsigned long long r;
    asm("mov.b64 %0, {%1, %2};" : "=l"(r) : "f"(lo), "f"(hi));
    return r;
}
__device__ __forceinline__ void unpack2(unsigned long long v, float& lo, float& hi) {
    asm("mov.b64 {%0, %1}, %2;" : "=f"(lo), "=f"(hi) : "l"(v));
}
__device__ __forceinline__ unsigned long long fma2(
    unsigned long long a, unsigned long long b, unsigned long long c) {
    unsigned long long d;
    asm("fma.rn.f32x2 %0, %1, %2, %3;" : "=l"(d) : "l"(a), "l"(b), "l"(c));
    return d;
}

// ---------------- 0) dtype detection ------------------------------------------
__global__ void detect_kernel(const int* __restrict__ ei_raw) {
    __shared__ int nz;
    if (threadIdx.x == 0) nz = 0;
    __syncthreads();
    int local = 0;
    for (int i = threadIdx.x; i < 4096; i += blockDim.x)
        if (ei_raw[2 * i + 1] != 0) local = 1;
    if (local) atomicOr(&nz, 1);
    __syncthreads();
    if (threadIdx.x == 0) g_is64 = (nz == 0) ? 1 : 0;
}

// ---------------- 1) SGEMM + fused attention halves ---------------------------
__global__ __launch_bounds__(256) void gemm_kernel(
    const float* __restrict__ x, const float* __restrict__ W,
    const float* __restrict__ att_src, const float* __restrict__ att_dst)
{
    __shared__ float xs[32][64];    // [k][row]
    __shared__ float ws[32][256];   // [k][col]

    const int tid = threadIdx.x;
    const int tx = tid & 15;
    const int ty = tid >> 4;
    const int lane = tid & 31;
    const int rowBase = blockIdx.x * 64;

    unsigned long long acc2[4][8];
#pragma unroll
    for (int r = 0; r < 4; r++)
#pragma unroll
        for (int c = 0; c < 8; c++) acc2[r][c] = 0ull;

    for (int k0 = 0; k0 < INC; k0 += 32) {
#pragma unroll
        for (int i = 0; i < 2; i++) {
            int t = tid + i * 256;
            int r = t >> 3;
            int kk = (t & 7) * 4;
            float4 v = make_float4(0.f, 0.f, 0.f, 0.f);
            int gr = rowBase + r;
            if (gr < NN) v = *(const float4*)&x[(size_t)gr * INC + k0 + kk];
            xs[kk + 0][r] = v.x; xs[kk + 1][r] = v.y;
            xs[kk + 2][r] = v.z; xs[kk + 3][r] = v.w;
        }
#pragma unroll
        for (int i = 0; i < 8; i++) {
            int t = tid + i * 256;
            int c = t >> 3;
            int kk = (t & 7) * 4;
            float4 v = *(const float4*)&W[(size_t)c * INC + k0 + kk];
            ws[kk + 0][c] = v.x; ws[kk + 1][c] = v.y;
            ws[kk + 2][c] = v.z; ws[kk + 3][c] = v.w;
        }
        __syncthreads();

#pragma unroll
        for (int k = 0; k < 32; k++) {
            float4 xf = *(const float4*)&xs[k][ty * 4];
            unsigned long long xp[4];
            xp[0] = pack2(xf.x, xf.x);
            xp[1] = pack2(xf.y, xf.y);
            xp[2] = pack2(xf.z, xf.z);
            xp[3] = pack2(xf.w, xf.w);
            const ulonglong2* wrow = (const ulonglong2*)&ws[k][tx * 16];
#pragma unroll
            for (int q = 0; q < 4; q++) {
                ulonglong2 wv = wrow[q];
#pragma unroll
                for (int r = 0; r < 4; r++) {
                    acc2[r][2 * q + 0] = fma2(xp[r], wv.x, acc2[r][2 * q + 0]);
                    acc2[r][2 * q + 1] = fma2(xp[r], wv.y, acc2[r][2 * q + 1]);
                }
            }
        }
        __syncthreads();
    }

    float acc[4][16];
#pragma unroll
    for (int r = 0; r < 4; r++)
#pragma unroll
        for (int c = 0; c < 8; c++)
            unpack2(acc2[r][c], acc[r][2 * c], acc[r][2 * c + 1]);

#pragma unroll
    for (int r = 0; r < 4; r++) {
        int gr = rowBase + ty * 4 + r;
        if (gr >= NN) continue;
        float* hp = &g_h[(size_t)gr * HC + tx * 16];
#pragma unroll
        for (int q = 0; q < 4; q++)
            *(float4*)&hp[q * 4] = *(float4*)&acc[r][q * 4];
    }

    const int head = tx >> 2;
    const int off = (tx & 3) * 16;
    float av[16], bv[16];
#pragma unroll
    for (int q = 0; q < 4; q++) {
        *(float4*)&av[q * 4] = *(const float4*)&att_src[head * OUTC + off + q * 4];
        *(float4*)&bv[q * 4] = *(const float4*)&att_dst[head * OUTC + off + q * 4];
    }
#pragma unroll
    for (int r = 0; r < 4; r++) {
        float s = 0.0f, d = 0.0f;
#pragma unroll
        for (int q = 0; q < 16; q++) {
            s = fmaf(acc[r][q], av[q], s);
            d = fmaf(acc[r][q], bv[q], d);
        }
        s += __shfl_xor_sync(0xffffffffu, s, 1);
        s += __shfl_xor_sync(0xffffffffu, s, 2);
        d += __shfl_xor_sync(0xffffffffu, d, 1);
        d += __shfl_xor_sync(0xffffffffu, d, 2);
        int gr = rowBase + ty * 4 + r;
        if ((lane & 3) == 0 && gr < NN) {
            g_asrc[gr * HEADS + head] = s;
            g_adst[gr * HEADS + head] = d;
        }
    }
}

// ---------------- 2) CSR build --------------------------------------------------
__global__ void zero_deg_kernel() {
    int i = blockIdx.x * blockDim.x + threadIdx.x;
    if (i < NN) g_deg[i] = 0;
}

__global__ void count_kernel(const void* __restrict__ ei) {
    int e = blockIdx.x * blockDim.x + threadIdx.x;
    if (e >= NE) return;
    int dst = edge_at(ei, (long long)NE + e);
    atomicAdd(&g_deg[dst], 1);
}

// single-block exclusive scan over g_deg -> g_off, g_pos
__global__ __launch_bounds__(1024) void scan_kernel() {
    const int tid = threadIdx.x;
    const int CH = (NN + 1023) / 1024;   // 49
    const int base = tid * CH;
    int s = 0;
#pragma unroll 4
    for (int i = 0; i < CH; i++) {
        int idx = base + i;
        if (idx < NN) s += g_deg[idx];
    }
    __shared__ int sm[1024];
    sm[tid] = s;
    __syncthreads();
    for (int off = 1; off < 1024; off <<= 1) {
        int v = (tid >= off) ? sm[tid - off] : 0;
        __syncthreads();
        sm[tid] += v;
        __syncthreads();
    }
    int run = sm[tid] - s;   // exclusive prefix of this thread's chunk
    for (int i = 0; i < CH; i++) {
        int idx = base + i;
        if (idx < NN) {
            g_off[idx] = run;
            g_pos[idx] = run;
            run += g_deg[idx];
        }
    }
    if (tid == 0) g_off[NN] = NE;
}

__global__ void fill_kernel(const void* __restrict__ ei) {
    int e = blockIdx.x * blockDim.x + threadIdx.x;
    if (e >= NE) return;
    int src = edge_at(ei, e);
    int dst = edge_at(ei, (long long)NE + e);
    int slot = atomicAdd(&g_pos[dst], 1);
    g_csr_src[slot] = src;
}

// ---------------- 3) gather: softmax + weighted sum + mean + bias + relu -------
// one warp per dst node; lane owns head=lane>>3, channels (lane&7)*8 .. +7
__global__ __launch_bounds__(256) void gather_kernel(
    float* __restrict__ out, const float* __restrict__ bias)
{
    int warp = (blockIdx.x * blockDim.x + threadIdx.x) >> 5;
    int lane = threadIdx.x & 31;
    if (warp >= NN) return;
    const int dst = warp;
    const int head = lane >> 3;
    const int coff = head * OUTC + (lane & 7) * 8;

    const float ad = g_adst[dst * HEADS + head];

    // self-loop seeds the accumulators (denominator always > 0)
    float ex = __expf(lrelu(g_asrc[dst * HEADS + head] + ad));
    float den = ex;
    float acc[8];
    {
        const float4* hp = (const float4*)&g_h[(size_t)dst * HC + coff];
        float4 p0 = hp[0], p1 = hp[1];
        acc[0] = ex * p0.x; acc[1] = ex * p0.y; acc[2] = ex * p0.z; acc[3] = ex * p0.w;
        acc[4] = ex * p1.x; acc[5] = ex * p1.y; acc[6] = ex * p1.z; acc[7] = ex * p1.w;
    }

    const int base = g_off[dst];
    const int end = g_off[dst + 1];
    for (int i = base; i < end; i += 32) {
        int mysrc = (i + lane < end) ? g_csr_src[i + lane] : 0;
        int cnt = min(32, end - i);
        for (int j = 0; j < cnt; j++) {
            int s = __shfl_sync(0xffffffffu, mysrc, j);
            float e = __expf(lrelu(__ldg(&g_asrc[s * HEADS + head]) + ad));
            const float4* sp = (const float4*)&g_h[(size_t)s * HC + coff];
            float4 q0 = sp[0], q1 = sp[1];
            den += e;
            acc[0] = fmaf(e, q0.x, acc[0]);
            acc[1] = fmaf(e, q0.y, acc[1]);
            acc[2] = fmaf(e, q0.z, acc[2]);
            acc[3] = fmaf(e, q0.w, acc[3]);
            acc[4] = fmaf(e, q1.x, acc[4]);
            acc[5] = fmaf(e, q1.y, acc[5]);
            acc[6] = fmaf(e, q1.z, acc[6]);
            acc[7] = fmaf(e, q1.w, acc[7]);
        }
    }

    // normalize per head, fold head-mean (x0.25)
    const float inv = 0.25f / den;
#pragma unroll
    for (int k = 0; k < 8; k++) acc[k] *= inv;

    // sum across the 4 heads (lanes differing in bits 3,4 of lane id)
#pragma unroll
    for (int k = 0; k < 8; k++) {
        acc[k] += __shfl_xor_sync(0xffffffffu, acc[k], 8);
        acc[k] += __shfl_xor_sync(0xffffffffu, acc[k], 16);
    }

    if (lane < 8) {
        float4 b0 = *(const float4*)&bias[lane * 8];
        float4 b1 = *(const float4*)&bias[lane * 8 + 4];
        float4 o0, o1;
        o0.x = fmaxf(acc[0] + b0.x, 0.0f);
        o0.y = fmaxf(acc[1] + b0.y, 0.0f);
        o0.z = fmaxf(acc[2] + b0.z, 0.0f);
        o0.w = fmaxf(acc[3] + b0.w, 0.0f);
        o1.x = fmaxf(acc[4] + b1.x, 0.0f);
        o1.y = fmaxf(acc[5] + b1.y, 0.0f);
        o1.z = fmaxf(acc[6] + b1.z, 0.0f);
        o1.w = fmaxf(acc[7] + b1.w, 0.0f);
        float4* op = (float4*)&out[(size_t)dst * OUTC + lane * 8];
        op[0] = o0;
        op[1] = o1;
    }
}

// ---------------- launch --------------------------------------------------------
extern "C" void kernel_launch(void* const* d_in, const int* in_sizes, int n_in,
                              void* d_out, int out_size)
{
    const float* x       = (const float*)d_in[0];
    const void*  ei      = d_in[1];
    const float* W       = (const float*)d_in[2];
    const float* att_src = (const float*)d_in[3];
    const float* att_dst = (const float*)d_in[4];
    const float* bias    = (const float*)d_in[5];
    float* out = (float*)d_out;

    detect_kernel<<<1, 256>>>((const int*)ei);
    zero_deg_kernel<<<(NN + 255) / 256, 256>>>();
    gemm_kernel<<<(NN + 63) / 64, 256>>>(x, W, att_src, att_dst);
    count_kernel<<<(NE + 255) / 256, 256>>>(ei);
    scan_kernel<<<1, 1024>>>();
    fill_kernel<<<(NE + 255) / 256, 256>>>(ei);
    gather_kernel<<<(NN * 32 + 255) / 256, 256>>>(out, bias);
}

// round 5
// speedup vs baseline: 1.8975x; 1.8975x over previous
#include <cuda_runtime.h>
#include <math.h>

// Problem constants (fixed by the reference)
#define NN 50000
#define NE 800000
#define INC 128
#define OUTC 64
#define HEADS 4
#define HC (HEADS * OUTC)   // 256
#define NEG_SLOPE 0.2f
#define ET (NE + NN)        // edges + self-loops

// ---------------- scratch (device globals) -----------------------------------
__device__ float g_h[(size_t)NN * HC];      // projected features [N,256]
__device__ float g_asrc[NN * HEADS];        // per-node att halves
__device__ float g_adst[NN * HEADS];
__device__ float g_den[NN * HEADS];         // segment sum of exp
__device__ float g_s[(size_t)ET * HEADS];   // per-edge exp(score)
__device__ int   g_is64;                    // edge_index dtype flag

// ---------------- helpers -----------------------------------------------------
__device__ __forceinline__ float lrelu(float v) {
    return v >= 0.0f ? v : NEG_SLOPE * v;
}

__device__ __forceinline__ int edge_at(const void* ei, long long idx) {
    if (g_is64) return (int)((const long long*)ei)[idx];
    return ((const int*)ei)[idx];
}

__device__ __forceinline__ unsigned long long pack2(float lo, float hi) {
    unsigned long long r;
    asm("mov.b64 %0, {%1, %2};" : "=l"(r) : "f"(lo), "f"(hi));
    return r;
}
__device__ __forceinline__ void unpack2(unsigned long long v, float& lo, float& hi) {
    asm("mov.b64 {%0, %1}, %2;" : "=f"(lo), "=f"(hi) : "l"(v));
}
__device__ __forceinline__ unsigned long long fma2(
    unsigned long long a, unsigned long long b, unsigned long long c) {
    unsigned long long d;
    asm("fma.rn.f32x2 %0, %1, %2, %3;" : "=l"(d) : "l"(a), "l"(b), "l"(c));
    return d;
}

__device__ __forceinline__ void red_add_v4(float* addr, float4 v) {
    asm volatile("red.global.add.v4.f32 [%0], {%1, %2, %3, %4};"
                 :: "l"(addr), "f"(v.x), "f"(v.y), "f"(v.z), "f"(v.w)
                 : "memory");
}

// ---------------- 0) dtype detection ------------------------------------------
__global__ void detect_kernel(const int* __restrict__ ei_raw) {
    __shared__ int nz;
    if (threadIdx.x == 0) nz = 0;
    __syncthreads();
    int local = 0;
    for (int i = threadIdx.x; i < 4096; i += blockDim.x)
        if (ei_raw[2 * i + 1] != 0) local = 1;
    if (local) atomicOr(&nz, 1);
    __syncthreads();
    if (threadIdx.x == 0) g_is64 = (nz == 0) ? 1 : 0;
}

// ---------------- 1) SGEMM + fused attention halves + den zero -----------------
// CTA: 64 rows x 256 cols, 256 threads, 8x8 microtile, f32x2 packed FMA.
__global__ __launch_bounds__(256) void gemm_kernel(
    const float* __restrict__ x, const float* __restrict__ W,
    const float* __restrict__ att_src, const float* __restrict__ att_dst)
{
    // fold den-zero into this kernel (782 blocks x 256 >= NN*HEADS)
    {
        int zi = blockIdx.x * 256 + threadIdx.x;
        if (zi < NN * HEADS) g_den[zi] = 0.0f;
    }

    __shared__ float xs[32][64];    // [k][row]
    __shared__ float ws[32][256];   // [k][col]

    const int tid = threadIdx.x;
    const int tcol = tid & 31;      // 32 col groups of 8
    const int trow = tid >> 5;      // 8 row groups of 8
    const int rowBase = blockIdx.x * 64;

    unsigned long long acc2[8][4];
#pragma unroll
    for (int r = 0; r < 8; r++)
#pragma unroll
        for (int c = 0; c < 4; c++) acc2[r][c] = 0ull;

    for (int k0 = 0; k0 < INC; k0 += 32) {
#pragma unroll
        for (int i = 0; i < 2; i++) {
            int t = tid + i * 256;
            int r = t >> 3;
            int kk = (t & 7) * 4;
            float4 v = make_float4(0.f, 0.f, 0.f, 0.f);
            int gr = rowBase + r;
            if (gr < NN) v = *(const float4*)&x[(size_t)gr * INC + k0 + kk];
            xs[kk + 0][r] = v.x; xs[kk + 1][r] = v.y;
            xs[kk + 2][r] = v.z; xs[kk + 3][r] = v.w;
        }
#pragma unroll
        for (int i = 0; i < 8; i++) {
            int t = tid + i * 256;
            int c = t >> 3;
            int kk = (t & 7) * 4;
            float4 v = *(const float4*)&W[(size_t)c * INC + k0 + kk];
            ws[kk + 0][c] = v.x; ws[kk + 1][c] = v.y;
            ws[kk + 2][c] = v.z; ws[kk + 3][c] = v.w;
        }
        __syncthreads();

#pragma unroll
        for (int k = 0; k < 32; k++) {
            float4 xa = *(const float4*)&xs[k][trow * 8];
            float4 xb = *(const float4*)&xs[k][trow * 8 + 4];
            ulonglong2 w0 = *(const ulonglong2*)&ws[k][tcol * 8];
            ulonglong2 w1 = *(const ulonglong2*)&ws[k][tcol * 8 + 4];
            unsigned long long wv[4] = {w0.x, w0.y, w1.x, w1.y};
            float xv[8] = {xa.x, xa.y, xa.z, xa.w, xb.x, xb.y, xb.z, xb.w};
#pragma unroll
            for (int r = 0; r < 8; r++) {
                unsigned long long xp = pack2(xv[r], xv[r]);
#pragma unroll
                for (int c = 0; c < 4; c++)
                    acc2[r][c] = fma2(xp, wv[c], acc2[r][c]);
            }
        }
        __syncthreads();
    }

    float acc[8][8];
#pragma unroll
    for (int r = 0; r < 8; r++)
#pragma unroll
        for (int c = 0; c < 4; c++)
            unpack2(acc2[r][c], acc[r][2 * c], acc[r][2 * c + 1]);

    // store h: thread covers rows rowBase+trow*8+r, cols tcol*8..+7
#pragma unroll
    for (int r = 0; r < 8; r++) {
        int gr = rowBase + trow * 8 + r;
        if (gr >= NN) continue;
        float* hp = &g_h[(size_t)gr * HC + tcol * 8];
        *(float4*)&hp[0] = *(float4*)&acc[r][0];
        *(float4*)&hp[4] = *(float4*)&acc[r][4];
    }

    // fused attention halves: head = tcol>>3, within-head offset (tcol&7)*8
    const int head = tcol >> 3;
    const int off = (tcol & 7) * 8;
    float av[8], bv[8];
    *(float4*)&av[0] = *(const float4*)&att_src[head * OUTC + off];
    *(float4*)&av[4] = *(const float4*)&att_src[head * OUTC + off + 4];
    *(float4*)&bv[0] = *(const float4*)&att_dst[head * OUTC + off];
    *(float4*)&bv[4] = *(const float4*)&att_dst[head * OUTC + off + 4];
#pragma unroll
    for (int r = 0; r < 8; r++) {
        float s = 0.0f, d = 0.0f;
#pragma unroll
        for (int q = 0; q < 8; q++) {
            s = fmaf(acc[r][q], av[q], s);
            d = fmaf(acc[r][q], bv[q], d);
        }
        s += __shfl_xor_sync(0xffffffffu, s, 1);
        s += __shfl_xor_sync(0xffffffffu, s, 2);
        s += __shfl_xor_sync(0xffffffffu, s, 4);
        d += __shfl_xor_sync(0xffffffffu, d, 1);
        d += __shfl_xor_sync(0xffffffffu, d, 2);
        d += __shfl_xor_sync(0xffffffffu, d, 4);
        int gr = rowBase + trow * 8 + r;
        if ((tcol & 7) == 0 && gr < NN) {
            g_asrc[gr * HEADS + head] = s;
            g_adst[gr * HEADS + head] = d;
        }
    }
}

// ---------------- 2) edge pass: score + exp + segment sum + out zero ----------
__global__ void edge_kernel(const void* __restrict__ ei, float* __restrict__ out)
{
    int e = blockIdx.x * blockDim.x + threadIdx.x;
    // fold out-zeroing here (ET threads >= NN*OUTC/4 float4 stores)
    if (e < NN * OUTC / 4)
        ((float4*)out)[e] = make_float4(0.f, 0.f, 0.f, 0.f);
    if (e >= ET) return;
    int src, dst;
    if (e < NE) {
        src = edge_at(ei, e);
        dst = edge_at(ei, (long long)NE + e);
    } else {
        src = dst = e - NE;
    }
    float4 as = *(const float4*)&g_asrc[src * HEADS];
    float4 ad = *(const float4*)&g_adst[dst * HEADS];
    float4 ex;
    ex.x = __expf(lrelu(as.x + ad.x));
    ex.y = __expf(lrelu(as.y + ad.y));
    ex.z = __expf(lrelu(as.z + ad.z));
    ex.w = __expf(lrelu(as.w + ad.w));
    *(float4*)&g_s[(size_t)e * HEADS] = ex;
    red_add_v4(&g_den[dst * HEADS], ex);
}

// ---------------- 3) weighted scatter (head-mean folded, vector RED) ----------
// half-warp per edge; lane j in 0..15 handles channels 4j..4j+3
__global__ __launch_bounds__(256) void scatter_kernel(
    const void* __restrict__ ei, float* __restrict__ out)
{
    int gtid = blockIdx.x * blockDim.x + threadIdx.x;
    int e = (gtid >> 5) * 2 + ((gtid & 31) >> 4);
    int j = gtid & 15;
    if (e >= ET) return;
    int src, dst;
    if (e < NE) {
        src = edge_at(ei, e);
        dst = edge_at(ei, (long long)NE + e);
    } else {
        src = dst = e - NE;
    }
    float4 ex = *(const float4*)&g_s[(size_t)e * HEADS];
    float4 dn = *(const float4*)&g_den[dst * HEADS];
    float a0 = 0.25f * ex.x / dn.x;
    float a1 = 0.25f * ex.y / dn.y;
    float a2 = 0.25f * ex.z / dn.z;
    float a3 = 0.25f * ex.w / dn.w;

    const float4* hp = (const float4*)&g_h[(size_t)src * HC];
    float4 h0 = hp[j];
    float4 h1 = hp[16 + j];
    float4 h2 = hp[32 + j];
    float4 h3 = hp[48 + j];
    float4 v;
    v.x = a0 * h0.x + a1 * h1.x + a2 * h2.x + a3 * h3.x;
    v.y = a0 * h0.y + a1 * h1.y + a2 * h2.y + a3 * h3.y;
    v.z = a0 * h0.z + a1 * h1.z + a2 * h2.z + a3 * h3.z;
    v.w = a0 * h0.w + a1 * h1.w + a2 * h2.w + a3 * h3.w;
    red_add_v4(&out[(size_t)dst * OUTC + 4 * j], v);
}

// ---------------- 4) finalize: bias + ReLU in place ----------------------------
__global__ void final_kernel(float* __restrict__ out, const float* __restrict__ bias)
{
    int i = blockIdx.x * blockDim.x + threadIdx.x;
    if (i >= NN * OUTC) return;
    float v = out[i] + bias[i & (OUTC - 1)];
    out[i] = fmaxf(v, 0.0f);
}

// ---------------- launch --------------------------------------------------------
extern "C" void kernel_launch(void* const* d_in, const int* in_sizes, int n_in,
                              void* d_out, int out_size)
{
    const float* x       = (const float*)d_in[0];
    const void*  ei      = d_in[1];
    const float* W       = (const float*)d_in[2];
    const float* att_src = (const float*)d_in[3];
    const float* att_dst = (const float*)d_in[4];
    const float* bias    = (const float*)d_in[5];
    float* out = (float*)d_out;

    detect_kernel<<<1, 256>>>((const int*)ei);                       // idx 0
    gemm_kernel<<<(NN + 63) / 64, 256>>>(x, W, att_src, att_dst);    // idx 1
    edge_kernel<<<(ET + 255) / 256, 256>>>(ei, out);                 // idx 2
    scatter_kernel<<<((size_t)ET * 16 + 255) / 256, 256>>>(ei, out); // idx 3 (profiled)
    final_kernel<<<(NN * OUTC + 255) / 256, 256>>>(out, bias);       // idx 4
}

// round 6
// speedup vs baseline: 1.9103x; 1.0068x over previous
#include <cuda_runtime.h>
#include <math.h>

// Problem constants (fixed by the reference)
#define NN 50000
#define NE 800000
#define INC 128
#define OUTC 64
#define HEADS 4
#define HC (HEADS * OUTC)   // 256
#define NEG_SLOPE 0.2f
#define ET (NE + NN)        // edges + self-loops

// ---------------- scratch (device globals) -----------------------------------
__device__ float g_h[(size_t)NN * HC];      // projected features [N,256]
__device__ float g_asrc[NN * HEADS];        // per-node att halves
__device__ float g_adst[NN * HEADS];
__device__ float g_den[NN * HEADS];         // segment sum of exp
__device__ int   g_is64;                    // edge_index dtype flag

// ---------------- helpers -----------------------------------------------------
__device__ __forceinline__ float lrelu(float v) {
    return v >= 0.0f ? v : NEG_SLOPE * v;
}

__device__ __forceinline__ int edge_at(const void* ei, long long idx) {
    if (g_is64) return (int)((const long long*)ei)[idx];
    return ((const int*)ei)[idx];
}

__device__ __forceinline__ unsigned long long pack2(float lo, float hi) {
    unsigned long long r;
    asm("mov.b64 %0, {%1, %2};" : "=l"(r) : "f"(lo), "f"(hi));
    return r;
}
__device__ __forceinline__ void unpack2(unsigned long long v, float& lo, float& hi) {
    asm("mov.b64 {%0, %1}, %2;" : "=f"(lo), "=f"(hi) : "l"(v));
}
__device__ __forceinline__ unsigned long long fma2(
    unsigned long long a, unsigned long long b, unsigned long long c) {
    unsigned long long d;
    asm("fma.rn.f32x2 %0, %1, %2, %3;" : "=l"(d) : "l"(a), "l"(b), "l"(c));
    return d;
}

__device__ __forceinline__ void red_add_v4(float* addr, float4 v) {
    asm volatile("red.global.add.v4.f32 [%0], {%1, %2, %3, %4};"
                 :: "l"(addr), "f"(v.x), "f"(v.y), "f"(v.z), "f"(v.w)
                 : "memory");
}

// ---------------- 0) dtype detection ------------------------------------------
__global__ void detect_kernel(const int* __restrict__ ei_raw) {
    __shared__ int nz;
    if (threadIdx.x == 0) nz = 0;
    __syncthreads();
    int local = 0;
    for (int i = threadIdx.x; i < 4096; i += blockDim.x)
        if (ei_raw[2 * i + 1] != 0) local = 1;
    if (local) atomicOr(&nz, 1);
    __syncthreads();
    if (threadIdx.x == 0) g_is64 = (nz == 0) ? 1 : 0;
}

// ---------------- 1) zero kernels (also launch-order fillers) ------------------
__global__ void zero_den_kernel() {
    int i = blockIdx.x * blockDim.x + threadIdx.x;
    if (i < NN * HEADS) g_den[i] = 0.0f;
}
__global__ void zero_out_kernel(float* __restrict__ out) {
    int i = blockIdx.x * blockDim.x + threadIdx.x;
    if (i < NN * OUTC / 4)
        ((float4*)out)[i] = make_float4(0.f, 0.f, 0.f, 0.f);
}

// ---------------- 2) SGEMM + fused attention halves (double buffered) ----------
// CTA: 64 rows x 256 cols, 256 threads, 8x8 microtile, f32x2 packed FMA.
__global__ __launch_bounds__(256) void gemm_kernel(
    const float* __restrict__ x, const float* __restrict__ W,
    const float* __restrict__ att_src, const float* __restrict__ att_dst)
{
    __shared__ float xs[2][32][64];    // [buf][k][row]  2x8KB
    __shared__ float ws[2][32][256];   // [buf][k][col]  2x32KB

    const int tid = threadIdx.x;
    const int tcol = tid & 31;      // 32 col groups of 8
    const int trow = tid >> 5;      // 8 row groups of 8
    const int rowBase = blockIdx.x * 64;

    // per-thread load coordinates (constant across chunks)
    const int xr0 = tid >> 3;            // xs row for part 0 (0..31)
    const int xr1 = (tid + 256) >> 3;    // xs row for part 1 (32..63)
    const int xkk = (tid & 7) * 4;       // k sub-offset
    const int wc = tid >> 3;             // base ws col pattern

    float4 px[2];      // x prefetch regs
    float4 pw[8];      // w prefetch regs

    // prologue: load chunk 0
    {
        int gr0 = rowBase + xr0, gr1 = rowBase + xr1;
        px[0] = (gr0 < NN) ? *(const float4*)&x[(size_t)gr0 * INC + xkk]
                           : make_float4(0.f, 0.f, 0.f, 0.f);
        px[1] = (gr1 < NN) ? *(const float4*)&x[(size_t)gr1 * INC + xkk]
                           : make_float4(0.f, 0.f, 0.f, 0.f);
#pragma unroll
        for (int i = 0; i < 8; i++) {
            int c = wc + i * 32;
            pw[i] = *(const float4*)&W[(size_t)c * INC + xkk];
        }
        xs[0][xkk + 0][xr0] = px[0].x; xs[0][xkk + 1][xr0] = px[0].y;
        xs[0][xkk + 2][xr0] = px[0].z; xs[0][xkk + 3][xr0] = px[0].w;
        xs[0][xkk + 0][xr1] = px[1].x; xs[0][xkk + 1][xr1] = px[1].y;
        xs[0][xkk + 2][xr1] = px[1].z; xs[0][xkk + 3][xr1] = px[1].w;
#pragma unroll
        for (int i = 0; i < 8; i++) {
            int c = wc + i * 32;
            ws[0][xkk + 0][c] = pw[i].x; ws[0][xkk + 1][c] = pw[i].y;
            ws[0][xkk + 2][c] = pw[i].z; ws[0][xkk + 3][c] = pw[i].w;
        }
    }
    __syncthreads();

    unsigned long long acc2[8][4];
#pragma unroll
    for (int r = 0; r < 8; r++)
#pragma unroll
        for (int c = 0; c < 4; c++) acc2[r][c] = 0ull;

#pragma unroll
    for (int ch = 0; ch < 4; ch++) {
        const int buf = ch & 1;
        // prefetch next chunk into regs
        if (ch < 3) {
            int k0 = (ch + 1) * 32;
            int gr0 = rowBase + xr0, gr1 = rowBase + xr1;
            px[0] = (gr0 < NN) ? *(const float4*)&x[(size_t)gr0 * INC + k0 + xkk]
                               : make_float4(0.f, 0.f, 0.f, 0.f);
            px[1] = (gr1 < NN) ? *(const float4*)&x[(size_t)gr1 * INC + k0 + xkk]
                               : make_float4(0.f, 0.f, 0.f, 0.f);
#pragma unroll
            for (int i = 0; i < 8; i++) {
                int c = wc + i * 32;
                pw[i] = *(const float4*)&W[(size_t)c * INC + k0 + xkk];
            }
        }

#pragma unroll
        for (int k = 0; k < 32; k++) {
            float4 xa = *(const float4*)&xs[buf][k][trow * 8];
            float4 xb = *(const float4*)&xs[buf][k][trow * 8 + 4];
            ulonglong2 w0 = *(const ulonglong2*)&ws[buf][k][tcol * 8];
            ulonglong2 w1 = *(const ulonglong2*)&ws[buf][k][tcol * 8 + 4];
            unsigned long long wv[4] = {w0.x, w0.y, w1.x, w1.y};
            float xv[8] = {xa.x, xa.y, xa.z, xa.w, xb.x, xb.y, xb.z, xb.w};
#pragma unroll
            for (int r = 0; r < 8; r++) {
                unsigned long long xp = pack2(xv[r], xv[r]);
#pragma unroll
                for (int c = 0; c < 4; c++)
                    acc2[r][c] = fma2(xp, wv[c], acc2[r][c]);
            }
        }

        // store prefetched regs to the other buffer
        if (ch < 3) {
            const int nb = buf ^ 1;
            xs[nb][xkk + 0][xr0] = px[0].x; xs[nb][xkk + 1][xr0] = px[0].y;
            xs[nb][xkk + 2][xr0] = px[0].z; xs[nb][xkk + 3][xr0] = px[0].w;
            xs[nb][xkk + 0][xr1] = px[1].x; xs[nb][xkk + 1][xr1] = px[1].y;
            xs[nb][xkk + 2][xr1] = px[1].z; xs[nb][xkk + 3][xr1] = px[1].w;
#pragma unroll
            for (int i = 0; i < 8; i++) {
                int c = wc + i * 32;
                ws[nb][xkk + 0][c] = pw[i].x; ws[nb][xkk + 1][c] = pw[i].y;
                ws[nb][xkk + 2][c] = pw[i].z; ws[nb][xkk + 3][c] = pw[i].w;
            }
            __syncthreads();
        }
    }

    float acc[8][8];
#pragma unroll
    for (int r = 0; r < 8; r++)
#pragma unroll
        for (int c = 0; c < 4; c++)
            unpack2(acc2[r][c], acc[r][2 * c], acc[r][2 * c + 1]);

    // store h
#pragma unroll
    for (int r = 0; r < 8; r++) {
        int gr = rowBase + trow * 8 + r;
        if (gr >= NN) continue;
        float* hp = &g_h[(size_t)gr * HC + tcol * 8];
        *(float4*)&hp[0] = *(float4*)&acc[r][0];
        *(float4*)&hp[4] = *(float4*)&acc[r][4];
    }

    // fused attention halves: head = tcol>>3, within-head offset (tcol&7)*8
    const int head = tcol >> 3;
    const int off = (tcol & 7) * 8;
    float av[8], bv[8];
    *(float4*)&av[0] = *(const float4*)&att_src[head * OUTC + off];
    *(float4*)&av[4] = *(const float4*)&att_src[head * OUTC + off + 4];
    *(float4*)&bv[0] = *(const float4*)&att_dst[head * OUTC + off];
    *(float4*)&bv[4] = *(const float4*)&att_dst[head * OUTC + off + 4];
#pragma unroll
    for (int r = 0; r < 8; r++) {
        float s = 0.0f, d = 0.0f;
#pragma unroll
        for (int q = 0; q < 8; q++) {
            s = fmaf(acc[r][q], av[q], s);
            d = fmaf(acc[r][q], bv[q], d);
        }
        s += __shfl_xor_sync(0xffffffffu, s, 1);
        s += __shfl_xor_sync(0xffffffffu, s, 2);
        s += __shfl_xor_sync(0xffffffffu, s, 4);
        d += __shfl_xor_sync(0xffffffffu, d, 1);
        d += __shfl_xor_sync(0xffffffffu, d, 2);
        d += __shfl_xor_sync(0xffffffffu, d, 4);
        int gr = rowBase + trow * 8 + r;
        if ((tcol & 7) == 0 && gr < NN) {
            g_asrc[gr * HEADS + head] = s;
            g_adst[gr * HEADS + head] = d;
        }
    }
}

// ---------------- 3) edge pass: denominator accumulation only ------------------
__global__ void edge_kernel(const void* __restrict__ ei)
{
    int e = blockIdx.x * blockDim.x + threadIdx.x;
    if (e >= ET) return;
    int src, dst;
    if (e < NE) {
        src = edge_at(ei, e);
        dst = edge_at(ei, (long long)NE + e);
    } else {
        src = dst = e - NE;
    }
    float4 as = *(const float4*)&g_asrc[src * HEADS];
    float4 ad = *(const float4*)&g_adst[dst * HEADS];
    float4 ex;
    ex.x = __expf(lrelu(as.x + ad.x));
    ex.y = __expf(lrelu(as.y + ad.y));
    ex.z = __expf(lrelu(as.z + ad.z));
    ex.w = __expf(lrelu(as.w + ad.w));
    red_add_v4(&g_den[dst * HEADS], ex);
}

// ---------------- 4) weighted scatter (ex recomputed, head-mean folded) --------
// half-warp per edge; lane j in 0..15 handles channels 4j..4j+3
__global__ __launch_bounds__(256) void scatter_kernel(
    const void* __restrict__ ei, float* __restrict__ out)
{
    int gtid = blockIdx.x * blockDim.x + threadIdx.x;
    int e = (gtid >> 5) * 2 + ((gtid & 31) >> 4);
    int j = gtid & 15;
    if (e >= ET) return;
    int src, dst;
    if (e < NE) {
        src = edge_at(ei, e);
        dst = edge_at(ei, (long long)NE + e);
    } else {
        src = dst = e - NE;
    }
    float4 as = *(const float4*)&g_asrc[src * HEADS];
    float4 ad = *(const float4*)&g_adst[dst * HEADS];
    float4 dn = *(const float4*)&g_den[dst * HEADS];
    float a0 = 0.25f * __expf(lrelu(as.x + ad.x)) / dn.x;
    float a1 = 0.25f * __expf(lrelu(as.y + ad.y)) / dn.y;
    float a2 = 0.25f * __expf(lrelu(as.z + ad.z)) / dn.z;
    float a3 = 0.25f * __expf(lrelu(as.w + ad.w)) / dn.w;

    const float4* hp = (const float4*)&g_h[(size_t)src * HC];
    float4 h0 = hp[j];
    float4 h1 = hp[16 + j];
    float4 h2 = hp[32 + j];
    float4 h3 = hp[48 + j];
    float4 v;
    v.x = a0 * h0.x + a1 * h1.x + a2 * h2.x + a3 * h3.x;
    v.y = a0 * h0.y + a1 * h1.y + a2 * h2.y + a3 * h3.y;
    v.z = a0 * h0.z + a1 * h1.z + a2 * h2.z + a3 * h3.z;
    v.w = a0 * h0.w + a1 * h1.w + a2 * h2.w + a3 * h3.w;
    red_add_v4(&out[(size_t)dst * OUTC + 4 * j], v);
}

// ---------------- 5) finalize: bias + ReLU in place ----------------------------
__global__ void final_kernel(float* __restrict__ out, const float* __restrict__ bias)
{
    int i = blockIdx.x * blockDim.x + threadIdx.x;
    if (i >= NN * OUTC) return;
    float v = out[i] + bias[i & (OUTC - 1)];
    out[i] = fmaxf(v, 0.0f);
}

// ---------------- launch --------------------------------------------------------
extern "C" void kernel_launch(void* const* d_in, const int* in_sizes, int n_in,
                              void* d_out, int out_size)
{
    const float* x       = (const float*)d_in[0];
    const void*  ei      = d_in[1];
    const float* W       = (const float*)d_in[2];
    const float* att_src = (const float*)d_in[3];
    const float* att_dst = (const float*)d_in[4];
    const float* bias    = (const float*)d_in[5];
    float* out = (float*)d_out;

    detect_kernel<<<1, 256>>>((const int*)ei);                       // idx 0
    zero_den_kernel<<<(NN * HEADS + 255) / 256, 256>>>();            // idx 1
    zero_out_kernel<<<(NN * OUTC / 4 + 255) / 256, 256>>>(out);      // idx 2
    gemm_kernel<<<(NN + 63) / 64, 256>>>(x, W, att_src, att_dst);    // idx 3 (profiled)
    edge_kernel<<<(ET + 255) / 256, 256>>>(ei);                      // idx 4
    scatter_kernel<<<((size_t)ET * 16 + 255) / 256, 256>>>(ei, out); // idx 5
    final_kernel<<<(NN * OUTC + 255) / 256, 256>>>(out, bias);       // idx 6
}

// round 7
// speedup vs baseline: 1.9523x; 1.0220x over previous
#include <cuda_runtime.h>
#include <math.h>

// Problem constants (fixed by the reference)
#define NN 50000
#define NE 800000
#define INC 128
#define OUTC 64
#define HEADS 4
#define HC (HEADS * OUTC)   // 256
#define NEG_SLOPE 0.2f
#define ET (NE + NN)        // edges + self-loops

// ---------------- scratch (device globals) -----------------------------------
__device__ float g_h[(size_t)NN * HC];      // projected features [N,256]
__device__ float g_asrc[NN * HEADS];        // per-node att halves
__device__ float g_adst[NN * HEADS];
__device__ float g_den[NN * HEADS];         // segment sum of exp
__device__ int   g_is64;                    // edge_index dtype flag

// ---------------- helpers -----------------------------------------------------
__device__ __forceinline__ float lrelu(float v) {
    return v >= 0.0f ? v : NEG_SLOPE * v;
}

__device__ __forceinline__ int edge_at(const void* ei, long long idx) {
    if (g_is64) return (int)((const long long*)ei)[idx];
    return ((const int*)ei)[idx];
}

__device__ __forceinline__ unsigned long long pack2(float lo, float hi) {
    unsigned long long r;
    asm("mov.b64 %0, {%1, %2};" : "=l"(r) : "f"(lo), "f"(hi));
    return r;
}
__device__ __forceinline__ void unpack2(unsigned long long v, float& lo, float& hi) {
    asm("mov.b64 {%0, %1}, %2;" : "=f"(lo), "=f"(hi) : "l"(v));
}
__device__ __forceinline__ unsigned long long fma2(
    unsigned long long a, unsigned long long b, unsigned long long c) {
    unsigned long long d;
    asm("fma.rn.f32x2 %0, %1, %2, %3;" : "=l"(d) : "l"(a), "l"(b), "l"(c));
    return d;
}

__device__ __forceinline__ void red_add_v4(float* addr, float4 v) {
    asm volatile("red.global.add.v4.f32 [%0], {%1, %2, %3, %4};"
                 :: "l"(addr), "f"(v.x), "f"(v.y), "f"(v.z), "f"(v.w)
                 : "memory");
}

// ---------------- 0) dtype detection ------------------------------------------
__global__ void detect_kernel(const int* __restrict__ ei_raw) {
    __shared__ int nz;
    if (threadIdx.x == 0) nz = 0;
    __syncthreads();
    int local = 0;
    for (int i = threadIdx.x; i < 4096; i += blockDim.x)
        if (ei_raw[2 * i + 1] != 0) local = 1;
    if (local) atomicOr(&nz, 1);
    __syncthreads();
    if (threadIdx.x == 0) g_is64 = (nz == 0) ? 1 : 0;
}

// ---------------- 1) zero kernels ----------------------------------------------
__global__ void zero_den_kernel() {
    int i = blockIdx.x * blockDim.x + threadIdx.x;
    if (i < NN * HEADS) g_den[i] = 0.0f;
}
__global__ void zero_out_kernel(float* __restrict__ out) {
    int i = blockIdx.x * blockDim.x + threadIdx.x;
    if (i < NN * OUTC / 4)
        ((float4*)out)[i] = make_float4(0.f, 0.f, 0.f, 0.f);
}

// ---------------- 2) SGEMM + fused attention halves ----------------------------
// CTA: 64 rows x 256 cols, 256 threads, 8x8 microtile, f32x2 packed FMA.
// Single smem buffer (40KB) + forced 2 CTAs/SM for latency hiding.
__global__ __launch_bounds__(256, 2) void gemm_kernel(
    const float* __restrict__ x, const float* __restrict__ W,
    const float* __restrict__ att_src, const float* __restrict__ att_dst)
{
    __shared__ float xs[32][64];    // [k][row]   8KB
    __shared__ float ws[32][256];   // [k][col]  32KB

    const int tid = threadIdx.x;
    const int tcol = tid & 31;      // 32 col groups of 8
    const int trow = tid >> 5;      // 8 row groups of 8
    const int rowBase = blockIdx.x * 64;

    unsigned long long acc2[8][4];
#pragma unroll
    for (int r = 0; r < 8; r++)
#pragma unroll
        for (int c = 0; c < 4; c++) acc2[r][c] = 0ull;

    for (int k0 = 0; k0 < INC; k0 += 32) {
#pragma unroll
        for (int i = 0; i < 2; i++) {
            int t = tid + i * 256;
            int r = t >> 3;
            int kk = (t & 7) * 4;
            float4 v = make_float4(0.f, 0.f, 0.f, 0.f);
            int gr = rowBase + r;
            if (gr < NN) v = *(const float4*)&x[(size_t)gr * INC + k0 + kk];
            xs[kk + 0][r] = v.x; xs[kk + 1][r] = v.y;
            xs[kk + 2][r] = v.z; xs[kk + 3][r] = v.w;
        }
#pragma unroll
        for (int i = 0; i < 8; i++) {
            int t = tid + i * 256;
            int c = t >> 3;
            int kk = (t & 7) * 4;
            float4 v = *(const float4*)&W[(size_t)c * INC + k0 + kk];
            ws[kk + 0][c] = v.x; ws[kk + 1][c] = v.y;
            ws[kk + 2][c] = v.z; ws[kk + 3][c] = v.w;
        }
        __syncthreads();

#pragma unroll
        for (int k = 0; k < 32; k++) {
            float4 xa = *(const float4*)&xs[k][trow * 8];
            float4 xb = *(const float4*)&xs[k][trow * 8 + 4];
            ulonglong2 w0 = *(const ulonglong2*)&ws[k][tcol * 8];
            ulonglong2 w1 = *(const ulonglong2*)&ws[k][tcol * 8 + 4];
            unsigned long long wv[4] = {w0.x, w0.y, w1.x, w1.y};
            float xv[8] = {xa.x, xa.y, xa.z, xa.w, xb.x, xb.y, xb.z, xb.w};
#pragma unroll
            for (int r = 0; r < 8; r++) {
                unsigned long long xp = pack2(xv[r], xv[r]);
#pragma unroll
                for (int c = 0; c < 4; c++)
                    acc2[r][c] = fma2(xp, wv[c], acc2[r][c]);
            }
        }
        __syncthreads();
    }

    float acc[8][8];
#pragma unroll
    for (int r = 0; r < 8; r++)
#pragma unroll
        for (int c = 0; c < 4; c++)
            unpack2(acc2[r][c], acc[r][2 * c], acc[r][2 * c + 1]);

    // store h
#pragma unroll
    for (int r = 0; r < 8; r++) {
        int gr = rowBase + trow * 8 + r;
        if (gr >= NN) continue;
        float* hp = &g_h[(size_t)gr * HC + tcol * 8];
        *(float4*)&hp[0] = *(float4*)&acc[r][0];
        *(float4*)&hp[4] = *(float4*)&acc[r][4];
    }

    // fused attention halves: head = tcol>>3, within-head offset (tcol&7)*8
    const int head = tcol >> 3;
    const int off = (tcol & 7) * 8;
    float av[8], bv[8];
    *(float4*)&av[0] = *(const float4*)&att_src[head * OUTC + off];
    *(float4*)&av[4] = *(const float4*)&att_src[head * OUTC + off + 4];
    *(float4*)&bv[0] = *(const float4*)&att_dst[head * OUTC + off];
    *(float4*)&bv[4] = *(const float4*)&att_dst[head * OUTC + off + 4];
#pragma unroll
    for (int r = 0; r < 8; r++) {
        float s = 0.0f, d = 0.0f;
#pragma unroll
        for (int q = 0; q < 8; q++) {
            s = fmaf(acc[r][q], av[q], s);
            d = fmaf(acc[r][q], bv[q], d);
        }
        s += __shfl_xor_sync(0xffffffffu, s, 1);
        s += __shfl_xor_sync(0xffffffffu, s, 2);
        s += __shfl_xor_sync(0xffffffffu, s, 4);
        d += __shfl_xor_sync(0xffffffffu, d, 1);
        d += __shfl_xor_sync(0xffffffffu, d, 2);
        d += __shfl_xor_sync(0xffffffffu, d, 4);
        int gr = rowBase + trow * 8 + r;
        if ((tcol & 7) == 0 && gr < NN) {
            g_asrc[gr * HEADS + head] = s;
            g_adst[gr * HEADS + head] = d;
        }
    }
}

// ---------------- 3) edge pass: denominator accumulation only ------------------
__global__ void edge_kernel(const void* __restrict__ ei)
{
    int e = blockIdx.x * blockDim.x + threadIdx.x;
    if (e >= ET) return;
    int src, dst;
    if (e < NE) {
        src = edge_at(ei, e);
        dst = edge_at(ei, (long long)NE + e);
    } else {
        src = dst = e - NE;
    }
    float4 as = *(const float4*)&g_asrc[src * HEADS];
    float4 ad = *(const float4*)&g_adst[dst * HEADS];
    float4 ex;
    ex.x = __expf(lrelu(as.x + ad.x));
    ex.y = __expf(lrelu(as.y + ad.y));
    ex.z = __expf(lrelu(as.z + ad.z));
    ex.w = __expf(lrelu(as.w + ad.w));
    red_add_v4(&g_den[dst * HEADS], ex);
}

// ---------------- 4) weighted scatter (ex recomputed, head-mean folded) --------
__global__ __launch_bounds__(256) void scatter_kernel(
    const void* __restrict__ ei, float* __restrict__ out)
{
    int gtid = blockIdx.x * blockDim.x + threadIdx.x;
    int e = (gtid >> 5) * 2 + ((gtid & 31) >> 4);
    int j = gtid & 15;
    if (e >= ET) return;
    int src, dst;
    if (e < NE) {
        src = edge_at(ei, e);
        dst = edge_at(ei, (long long)NE + e);
    } else {
        src = dst = e - NE;
    }
    float4 as = *(const float4*)&g_asrc[src * HEADS];
    float4 ad = *(const float4*)&g_adst[dst * HEADS];
    float4 dn = *(const float4*)&g_den[dst * HEADS];
    float a0 = 0.25f * __expf(lrelu(as.x + ad.x)) / dn.x;
    float a1 = 0.25f * __expf(lrelu(as.y + ad.y)) / dn.y;
    float a2 = 0.25f * __expf(lrelu(as.z + ad.z)) / dn.z;
    float a3 = 0.25f * __expf(lrelu(as.w + ad.w)) / dn.w;

    const float4* hp = (const float4*)&g_h[(size_t)src * HC];
    float4 h0 = hp[j];
    float4 h1 = hp[16 + j];
    float4 h2 = hp[32 + j];
    float4 h3 = hp[48 + j];
    float4 v;
    v.x = a0 * h0.x + a1 * h1.x + a2 * h2.x + a3 * h3.x;
    v.y = a0 * h0.y + a1 * h1.y + a2 * h2.y + a3 * h3.y;
    v.z = a0 * h0.z + a1 * h1.z + a2 * h2.z + a3 * h3.z;
    v.w = a0 * h0.w + a1 * h1.w + a2 * h2.w + a3 * h3.w;
    red_add_v4(&out[(size_t)dst * OUTC + 4 * j], v);
}

// ---------------- 5) finalize: bias + ReLU in place ----------------------------
__global__ void final_kernel(float* __restrict__ out, const float* __restrict__ bias)
{
    int i = blockIdx.x * blockDim.x + threadIdx.x;
    if (i >= NN * OUTC) return;
    float v = out[i] + bias[i & (OUTC - 1)];
    out[i] = fmaxf(v, 0.0f);
}

// ---------------- launch --------------------------------------------------------
extern "C" void kernel_launch(void* const* d_in, const int* in_sizes, int n_in,
                              void* d_out, int out_size)
{
    const float* x       = (const float*)d_in[0];
    const void*  ei      = d_in[1];
    const float* W       = (const float*)d_in[2];
    const float* att_src = (const float*)d_in[3];
    const float* att_dst = (const float*)d_in[4];
    const float* bias    = (const float*)d_in[5];
    float* out = (float*)d_out;

    detect_kernel<<<1, 256>>>((const int*)ei);                       // idx 0
    zero_den_kernel<<<(NN * HEADS + 255) / 256, 256>>>();            // idx 1
    zero_out_kernel<<<(NN * OUTC / 4 + 255) / 256, 256>>>(out);      // idx 2
    gemm_kernel<<<(NN + 63) / 64, 256>>>(x, W, att_src, att_dst);    // idx 3 (profiled)
    edge_kernel<<<(ET + 255) / 256, 256>>>(ei);                      // idx 4
    scatter_kernel<<<((size_t)ET * 16 + 255) / 256, 256>>>(ei, out); // idx 5
    final_kernel<<<(NN * OUTC + 255) / 256, 256>>>(out, bias);       // idx 6
}